// round 1
// baseline (speedup 1.0000x reference)
#include <cuda_runtime.h>
#include <math_constants.h>

// Problem dims
constexpr int BATCH = 8;
constexpr int DIM   = 512;
constexpr int SEQ   = 2048;

// Scratch: Q/K/V as [3][B][N][D], scores as [B][N][N]
__device__ float g_qkv[3][BATCH][SEQ][DIM];           // ~100.7 MB
__device__ float g_scores[(size_t)BATCH * SEQ * SEQ]; // ~134 MB

// ---------------------------------------------------------------------------
// Kernel 1: QKV projection.  out[which][b][n][d] = sum_c x[b][c][n]*W[d][c] + bias[d]
// grid: (DIM/128, SEQ/128, 3*BATCH), block 256
// ---------------------------------------------------------------------------
__global__ __launch_bounds__(256) void qkv_kernel(
    const float* __restrict__ x,
    const float* __restrict__ Wq, const float* __restrict__ bq,
    const float* __restrict__ Wk, const float* __restrict__ bk,
    const float* __restrict__ Wv, const float* __restrict__ bv)
{
    const int z     = blockIdx.z;
    const int b     = z % BATCH;
    const int which = z / BATCH;
    const float* W    = (which == 0) ? Wq : (which == 1) ? Wk : Wv;
    const float* bias = (which == 0) ? bq : (which == 1) ? bk : bv;
    float* out = &g_qkv[which][b][0][0];

    const int d0 = blockIdx.x * 128;   // output-dim tile (cols)
    const int n0 = blockIdx.y * 128;   // seq tile (rows)

    __shared__ float As[8][128];  // [c][n]
    __shared__ float Bs[8][128];  // [c][d]

    const int tid  = threadIdx.x;
    const int trow = tid >> 4;     // 0..15 -> n
    const int tcol = tid & 15;     // 0..15 -> d

    float acc[8][8] = {};
    const float* xb = x + (size_t)b * DIM * SEQ;

    for (int c0 = 0; c0 < DIM; c0 += 8) {
        {   // A: x[b][c][n], contiguous in n
            int k  = tid >> 5;            // 0..7
            int nv = (tid & 31) << 2;     // 0..124
            float4 v = *(const float4*)(xb + (size_t)(c0 + k) * SEQ + n0 + nv);
            As[k][nv + 0] = v.x; As[k][nv + 1] = v.y;
            As[k][nv + 2] = v.z; As[k][nv + 3] = v.w;
        }
        {   // B: W[d][c], contiguous in c -> transpose into smem
            int d  = tid >> 1;            // 0..127
            int cv = (tid & 1) << 2;      // 0 or 4
            float4 v = *(const float4*)(W + (size_t)(d0 + d) * DIM + c0 + cv);
            Bs[cv + 0][d] = v.x; Bs[cv + 1][d] = v.y;
            Bs[cv + 2][d] = v.z; Bs[cv + 3][d] = v.w;
        }
        __syncthreads();
        #pragma unroll
        for (int k = 0; k < 8; k++) {
            float a[8], bb[8];
            #pragma unroll
            for (int i = 0; i < 8; i++) a[i]  = As[k][trow * 8 + i];
            #pragma unroll
            for (int j = 0; j < 8; j++) bb[j] = Bs[k][tcol * 8 + j];
            #pragma unroll
            for (int i = 0; i < 8; i++)
                #pragma unroll
                for (int j = 0; j < 8; j++) acc[i][j] += a[i] * bb[j];
        }
        __syncthreads();
    }

    #pragma unroll
    for (int i = 0; i < 8; i++) {
        int n = n0 + trow * 8 + i;
        #pragma unroll
        for (int j = 0; j < 8; j += 4) {
            int d = d0 + tcol * 8 + j;
            float4 v;
            v.x = acc[i][j + 0] + bias[d + 0];
            v.y = acc[i][j + 1] + bias[d + 1];
            v.z = acc[i][j + 2] + bias[d + 2];
            v.w = acc[i][j + 3] + bias[d + 3];
            *(float4*)(out + (size_t)n * DIM + d) = v;
        }
    }
}

// ---------------------------------------------------------------------------
// Kernel 2: scores[b][n][m] = sum_d Q[b][n][d]*K[b][m][d]
// grid: (SEQ/128 (m), SEQ/128 (n), BATCH), block 256
// ---------------------------------------------------------------------------
__global__ __launch_bounds__(256) void scores_kernel()
{
    const int b  = blockIdx.z;
    const int m0 = blockIdx.x * 128;   // key tile (cols)
    const int n0 = blockIdx.y * 128;   // query tile (rows)

    const float* Q = &g_qkv[0][b][0][0];
    const float* K = &g_qkv[1][b][0][0];
    float* S = g_scores + (size_t)b * SEQ * SEQ;

    __shared__ float As[8][128];  // [d][n]
    __shared__ float Bs[8][128];  // [d][m]

    const int tid  = threadIdx.x;
    const int trow = tid >> 4;
    const int tcol = tid & 15;

    float acc[8][8] = {};

    for (int c0 = 0; c0 < DIM; c0 += 8) {
        {   // Q[n][d], contiguous in d -> transpose
            int r  = tid >> 1;
            int kv = (tid & 1) << 2;
            float4 v = *(const float4*)(Q + (size_t)(n0 + r) * DIM + c0 + kv);
            As[kv + 0][r] = v.x; As[kv + 1][r] = v.y;
            As[kv + 2][r] = v.z; As[kv + 3][r] = v.w;
        }
        {   // K[m][d], contiguous in d -> transpose
            int r  = tid >> 1;
            int kv = (tid & 1) << 2;
            float4 v = *(const float4*)(K + (size_t)(m0 + r) * DIM + c0 + kv);
            Bs[kv + 0][r] = v.x; Bs[kv + 1][r] = v.y;
            Bs[kv + 2][r] = v.z; Bs[kv + 3][r] = v.w;
        }
        __syncthreads();
        #pragma unroll
        for (int k = 0; k < 8; k++) {
            float a[8], bb[8];
            #pragma unroll
            for (int i = 0; i < 8; i++) a[i]  = As[k][trow * 8 + i];
            #pragma unroll
            for (int j = 0; j < 8; j++) bb[j] = Bs[k][tcol * 8 + j];
            #pragma unroll
            for (int i = 0; i < 8; i++)
                #pragma unroll
                for (int j = 0; j < 8; j++) acc[i][j] += a[i] * bb[j];
        }
        __syncthreads();
    }

    #pragma unroll
    for (int i = 0; i < 8; i++) {
        int n = n0 + trow * 8 + i;
        #pragma unroll
        for (int j = 0; j < 8; j += 4) {
            int m = m0 + tcol * 8 + j;
            float4 v = make_float4(acc[i][j], acc[i][j+1], acc[i][j+2], acc[i][j+3]);
            *(float4*)(S + (size_t)n * SEQ + m) = v;
        }
    }
}

// ---------------------------------------------------------------------------
// Kernel 3: row softmax over scores rows (length SEQ=2048), in place.
// grid: BATCH*SEQ blocks, 256 threads, 8 elements/thread.
// ---------------------------------------------------------------------------
__global__ __launch_bounds__(256) void softmax_kernel()
{
    const int row = blockIdx.x;                  // 0 .. BATCH*SEQ-1
    float* p = g_scores + (size_t)row * SEQ;
    const int t = threadIdx.x;

    float v[8];
    float mx = -CUDART_INF_F;
    #pragma unroll
    for (int i = 0; i < 8; i++) {
        v[i] = p[t + i * 256];
        mx = fmaxf(mx, v[i]);
    }

    __shared__ float red[8];
    #pragma unroll
    for (int o = 16; o > 0; o >>= 1) mx = fmaxf(mx, __shfl_xor_sync(0xffffffffu, mx, o));
    if ((t & 31) == 0) red[t >> 5] = mx;
    __syncthreads();
    mx = red[0];
    #pragma unroll
    for (int w = 1; w < 8; w++) mx = fmaxf(mx, red[w]);
    __syncthreads();

    float s = 0.f;
    #pragma unroll
    for (int i = 0; i < 8; i++) {
        v[i] = __expf(v[i] - mx);
        s += v[i];
    }
    #pragma unroll
    for (int o = 16; o > 0; o >>= 1) s += __shfl_xor_sync(0xffffffffu, s, o);
    if ((t & 31) == 0) red[t >> 5] = s;
    __syncthreads();
    s = red[0];
    #pragma unroll
    for (int w = 1; w < 8; w++) s += red[w];

    const float inv = 1.0f / s;
    #pragma unroll
    for (int i = 0; i < 8; i++) p[t + i * 256] = v[i] * inv;
}

// ---------------------------------------------------------------------------
// Kernel 4: out[b][d][n] = sum_m P[b][n][m] * V[b][m][d]
// Computed directly transposed: rows = d, cols = n -> coalesced output stores.
// grid: (SEQ/128 (n), DIM/128 (d), BATCH), block 256
// ---------------------------------------------------------------------------
__global__ __launch_bounds__(256) void out_kernel(float* __restrict__ out)
{
    const int b  = blockIdx.z;
    const int n0 = blockIdx.x * 128;   // cols (seq)
    const int d0 = blockIdx.y * 128;   // rows (dim)

    const float* V = &g_qkv[2][b][0][0];
    const float* P = g_scores + (size_t)b * SEQ * SEQ;

    __shared__ float As[8][128];  // [mk][d]
    __shared__ float Bs[8][128];  // [mk][n]

    const int tid  = threadIdx.x;
    const int trow = tid >> 4;     // -> d
    const int tcol = tid & 15;     // -> n

    float acc[8][8] = {};

    for (int k0 = 0; k0 < SEQ; k0 += 8) {
        {   // V[mk][d], contiguous in d
            int k  = tid >> 5;
            int dv = (tid & 31) << 2;
            float4 v = *(const float4*)(V + (size_t)(k0 + k) * DIM + d0 + dv);
            As[k][dv + 0] = v.x; As[k][dv + 1] = v.y;
            As[k][dv + 2] = v.z; As[k][dv + 3] = v.w;
        }
        {   // P[n][mk], contiguous in mk -> transpose
            int r  = tid >> 1;
            int kv = (tid & 1) << 2;
            float4 v = *(const float4*)(P + (size_t)(n0 + r) * SEQ + k0 + kv);
            Bs[kv + 0][r] = v.x; Bs[kv + 1][r] = v.y;
            Bs[kv + 2][r] = v.z; Bs[kv + 3][r] = v.w;
        }
        __syncthreads();
        #pragma unroll
        for (int k = 0; k < 8; k++) {
            float a[8], bb[8];
            #pragma unroll
            for (int i = 0; i < 8; i++) a[i]  = As[k][trow * 8 + i];
            #pragma unroll
            for (int j = 0; j < 8; j++) bb[j] = Bs[k][tcol * 8 + j];
            #pragma unroll
            for (int i = 0; i < 8; i++)
                #pragma unroll
                for (int j = 0; j < 8; j++) acc[i][j] += a[i] * bb[j];
        }
        __syncthreads();
    }

    float* ob = out + (size_t)b * DIM * SEQ;
    #pragma unroll
    for (int i = 0; i < 8; i++) {
        int d = d0 + trow * 8 + i;
        #pragma unroll
        for (int j = 0; j < 8; j += 4) {
            int n = n0 + tcol * 8 + j;
            float4 v = make_float4(acc[i][j], acc[i][j+1], acc[i][j+2], acc[i][j+3]);
            *(float4*)(ob + (size_t)d * SEQ + n) = v;
        }
    }
}

// ---------------------------------------------------------------------------
extern "C" void kernel_launch(void* const* d_in, const int* in_sizes, int n_in,
                              void* d_out, int out_size)
{
    (void)in_sizes; (void)n_in; (void)out_size;
    const float* x  = (const float*)d_in[0];
    const float* Wq = (const float*)d_in[1];
    const float* bq = (const float*)d_in[2];
    const float* Wk = (const float*)d_in[3];
    const float* bk = (const float*)d_in[4];
    const float* Wv = (const float*)d_in[5];
    const float* bv = (const float*)d_in[6];
    float* out = (float*)d_out;

    qkv_kernel<<<dim3(DIM / 128, SEQ / 128, 3 * BATCH), 256>>>(x, Wq, bq, Wk, bk, Wv, bv);
    scores_kernel<<<dim3(SEQ / 128, SEQ / 128, BATCH), 256>>>();
    softmax_kernel<<<BATCH * SEQ, 256>>>();
    out_kernel<<<dim3(SEQ / 128, DIM / 128, BATCH), 256>>>(out);
}

// round 3
// speedup vs baseline: 1.5815x; 1.5815x over previous
#include <cuda_runtime.h>
#include <cuda_bf16.h>
#include <cstdint>
#include <math_constants.h>

constexpr int BATCH = 8;
constexpr int DIM   = 512;
constexpr int SEQ   = 2048;

// ---------------------------------------------------------------------------
// Scratch (device globals; no allocation allowed)
// ---------------------------------------------------------------------------
__device__ __nv_bfloat16 g_q_hi[(size_t)BATCH * SEQ * DIM];
__device__ __nv_bfloat16 g_q_lo[(size_t)BATCH * SEQ * DIM];
__device__ __nv_bfloat16 g_k_hi[(size_t)BATCH * SEQ * DIM];
__device__ __nv_bfloat16 g_k_lo[(size_t)BATCH * SEQ * DIM];
__device__ __nv_bfloat16 g_v_hi[(size_t)BATCH * SEQ * DIM];
__device__ __nv_bfloat16 g_v_lo[(size_t)BATCH * SEQ * DIM];
__device__ float         g_scores[(size_t)BATCH * SEQ * SEQ];
__device__ __nv_bfloat16 g_p_hi[(size_t)BATCH * SEQ * SEQ];
__device__ __nv_bfloat16 g_p_lo[(size_t)BATCH * SEQ * SEQ];

// ---------------------------------------------------------------------------
// Helpers
// ---------------------------------------------------------------------------
__device__ __forceinline__ uint32_t smem_to_u32(const void* p) {
    uint32_t a;
    asm("{ .reg .u64 t; cvta.to.shared.u64 t, %1; cvt.u32.u64 %0, t; }" : "=r"(a) : "l"(p));
    return a;
}

// SW128 swizzle: 128B rows, conflict-free ldmatrix (16B unit' = unit ^ (row&7))
#define SWZ(x) ((x) ^ (((x) >> 3) & 0x70))

__device__ __forceinline__ void split2(float f, __nv_bfloat16& h, __nv_bfloat16& l) {
    h = __float2bfloat16(f);
    l = __float2bfloat16(f - __bfloat162float(h));
}
__device__ __forceinline__ uint32_t pack2(__nv_bfloat16 a, __nv_bfloat16 b) {
    __nv_bfloat162 t = __halves2bfloat162(a, b);
    return *reinterpret_cast<uint32_t*>(&t);
}

__device__ __forceinline__ void ldsm_x4(uint32_t* r, uint32_t addr) {
    asm volatile("ldmatrix.sync.aligned.m8n8.x4.shared.b16 {%0,%1,%2,%3}, [%4];"
        : "=r"(r[0]), "=r"(r[1]), "=r"(r[2]), "=r"(r[3]) : "r"(addr));
}

__device__ __forceinline__ void mma16816(float* c, const uint32_t* a, const uint32_t* b) {
    asm volatile(
        "mma.sync.aligned.m16n8k16.row.col.f32.bf16.bf16.f32 "
        "{%0,%1,%2,%3}, {%4,%5,%6,%7}, {%8,%9}, {%0,%1,%2,%3};"
        : "+f"(c[0]), "+f"(c[1]), "+f"(c[2]), "+f"(c[3])
        : "r"(a[0]), "r"(a[1]), "r"(a[2]), "r"(a[3]), "r"(b[0]), "r"(b[1]));
}

// SMEM layout: four 128x64 bf16 tiles (K-major rows of 128B, SW128 swizzled)
constexpr int OFF_AH = 0;
constexpr int OFF_AL = 16384;
constexpr int OFF_BH = 32768;
constexpr int OFF_BL = 49152;
constexpr int SMEM_BYTES = 65536;

// ---------------------------------------------------------------------------
// Consume one K-chunk (64) of split-MMA on the smem tiles.
// CTA tile 128(M) x 128(N); 8 warps as 4(M) x 2(N); warp tile 32x64.
// acc[tm][tn][4]: tm in 0..1 (16-row tiles), tn in 0..7 (8-col tiles).
// Computes acc += AH*BH + AL*BH + AH*BL  (lo*lo dropped).
// ---------------------------------------------------------------------------
__device__ __forceinline__ void mma_consume(uint32_t sb, float acc[2][8][4]) {
    const int lane = threadIdx.x & 31;
    const int wid  = threadIdx.x >> 5;
    const int wm   = (wid & 3) * 32;
    const int wn   = (wid >> 2) * 64;

    #pragma unroll
    for (int k16 = 0; k16 < 4; k16++) {
        uint32_t aH[2][4], aL[2][4], B[4][4];
        // A fragments: lanes 0-7 rows 0-7 @k0, 8-15 rows 8-15 @k0,
        //              16-23 rows 0-7 @k8, 24-31 rows 8-15 @k8
        #pragma unroll
        for (int tm = 0; tm < 2; tm++) {
            int r  = wm + tm * 16 + (lane & 15);
            int ku = k16 * 2 + (lane >> 4);
            uint32_t off = SWZ((uint32_t)(r * 128 + ku * 16));
            ldsm_x4(aH[tm], sb + OFF_AH + off);
            ldsm_x4(aL[tm], sb + OFF_AL + off);
        }
        // B-hi fragments: per x4 covers 16 n-rows x 16 k:
        //   lanes 0-7: n0-7 @k0, 8-15: n0-7 @k8, 16-23: n8-15 @k0, 24-31: n8-15 @k8
        #pragma unroll
        for (int tb = 0; tb < 4; tb++) {
            int g  = lane >> 3;
            int r  = wn + tb * 16 + (g >> 1) * 8 + (lane & 7);
            int ku = k16 * 2 + (g & 1);
            ldsm_x4(B[tb], sb + OFF_BH + SWZ((uint32_t)(r * 128 + ku * 16)));
        }
        #pragma unroll
        for (int tm = 0; tm < 2; tm++)
            #pragma unroll
            for (int tn = 0; tn < 8; tn++) {
                uint32_t bf[2] = { B[tn >> 1][(tn & 1) * 2 + 0] * 0u, 0u };
                // (select the right pair: even tn -> regs {0,1}, odd tn -> regs {2,3})
                bf[0] = B[tn >> 1][(tn & 1) ? 2 : 0];
                bf[1] = B[tn >> 1][(tn & 1) ? 3 : 1];
                mma16816(acc[tm][tn], aH[tm], bf);
                mma16816(acc[tm][tn], aL[tm], bf);
            }
        // B-lo fragments (reuse regs), only AH*BL
        #pragma unroll
        for (int tb = 0; tb < 4; tb++) {
            int g  = lane >> 3;
            int r  = wn + tb * 16 + (g >> 1) * 8 + (lane & 7);
            int ku = k16 * 2 + (g & 1);
            ldsm_x4(B[tb], sb + OFF_BL + SWZ((uint32_t)(r * 128 + ku * 16)));
        }
        #pragma unroll
        for (int tm = 0; tm < 2; tm++)
            #pragma unroll
            for (int tn = 0; tn < 8; tn++) {
                uint32_t bf[2];
                bf[0] = B[tn >> 1][(tn & 1) ? 2 : 0];
                bf[1] = B[tn >> 1][(tn & 1) ? 3 : 1];
                mma16816(acc[tm][tn], aH[tm], bf);
            }
    }
}

// ---------------------------------------------------------------------------
// Kernel 1: QKV projection.  y[n][d] = sum_c x[b][c][n] * W[d][c] + bias[d]
//   M = n (A rows), N = d (B rows), K = c.
//   A[n][c] = x[c][n] (fp32 transpose-in-load + split), B[d][c] = W (natural).
//   Epilogue: split bf16, write {q|k|v}_{hi,lo}[b][n][d].
// grid (SEQ/128, DIM/128, 3*BATCH), block 256
// ---------------------------------------------------------------------------
__global__ __launch_bounds__(256, 2) void qkv_kernel(
    const float* __restrict__ x,
    const float* __restrict__ Wq, const float* __restrict__ bq,
    const float* __restrict__ Wk, const float* __restrict__ bk,
    const float* __restrict__ Wv, const float* __restrict__ bv)
{
    extern __shared__ char smem[];
    const uint32_t sb = smem_to_u32(smem);
    const int tid = threadIdx.x;
    const int z = blockIdx.z, which = z >> 3, b = z & 7;
    const float* W    = (which == 0) ? Wq : (which == 1) ? Wk : Wv;
    const float* bias = (which == 0) ? bq : (which == 1) ? bk : bv;
    __nv_bfloat16* out_hi = (which == 0) ? g_q_hi : (which == 1) ? g_k_hi : g_v_hi;
    __nv_bfloat16* out_lo = (which == 0) ? g_q_lo : (which == 1) ? g_k_lo : g_v_lo;

    const int n0 = blockIdx.x * 128;
    const int d0 = blockIdx.y * 128;
    const float* xb = x + (size_t)b * DIM * SEQ;

    float acc[2][8][4] = {};

    for (int ch = 0; ch < DIM / 64; ++ch) {
        const int c0 = ch * 64;
        // A[n][c] = x[c][n]: coalesced read along n, scattered split stores
        #pragma unroll
        for (int i = 0; i < 8; i++) {
            int idx = tid + i * 256;          // 2048 float4s
            int c   = idx >> 5;               // 0..63
            int n4  = (idx & 31) << 2;        // 0..124
            float4 v = *(const float4*)(xb + (size_t)(c0 + c) * SEQ + n0 + n4);
            float f[4] = {v.x, v.y, v.z, v.w};
            #pragma unroll
            for (int j = 0; j < 4; j++) {
                __nv_bfloat16 h, l; split2(f[j], h, l);
                uint32_t sw = SWZ((uint32_t)((n4 + j) * 128 + c * 2));
                *(__nv_bfloat16*)(smem + OFF_AH + sw) = h;
                *(__nv_bfloat16*)(smem + OFF_AL + sw) = l;
            }
        }
        // B[d][c] = W[d][c]: natural, vectorized split stores
        #pragma unroll
        for (int i = 0; i < 8; i++) {
            int idx = tid + i * 256;
            int r   = idx >> 4;               // 0..127 (d row)
            int c4  = (idx & 15) << 2;        // 0..60
            float4 v = *(const float4*)(W + (size_t)(d0 + r) * DIM + c0 + c4);
            __nv_bfloat16 h0,h1,h2,h3,l0,l1,l2,l3;
            split2(v.x, h0, l0); split2(v.y, h1, l1);
            split2(v.z, h2, l2); split2(v.w, h3, l3);
            uint32_t sw = SWZ((uint32_t)(r * 128 + c4 * 2));
            *(uint2*)(smem + OFF_BH + sw) = make_uint2(pack2(h0,h1), pack2(h2,h3));
            *(uint2*)(smem + OFF_BL + sw) = make_uint2(pack2(l0,l1), pack2(l2,l3));
        }
        __syncthreads();
        mma_consume(sb, acc);
        __syncthreads();
    }

    // Epilogue
    const int lane = tid & 31, wid = tid >> 5;
    const int g = lane >> 2, t = lane & 3;
    const int wm = (wid & 3) * 32, wn = (wid >> 2) * 64;
    #pragma unroll
    for (int tn = 0; tn < 8; tn++) {
        const int d = d0 + wn + tn * 8 + t * 2;
        const float b0 = bias[d], b1 = bias[d + 1];
        #pragma unroll
        for (int tm = 0; tm < 2; tm++)
            #pragma unroll
            for (int h = 0; h < 2; h++) {
                int n = n0 + wm + tm * 16 + g + h * 8;
                float f0 = acc[tm][tn][2 * h + 0] + b0;
                float f1 = acc[tm][tn][2 * h + 1] + b1;
                __nv_bfloat16 h0, l0, h1, l1;
                split2(f0, h0, l0); split2(f1, h1, l1);
                size_t off = ((size_t)b * SEQ + n) * DIM + d;
                *(uint32_t*)(out_hi + off) = pack2(h0, h1);
                *(uint32_t*)(out_lo + off) = pack2(l0, l1);
            }
    }
}

// ---------------------------------------------------------------------------
// Kernel 2: scores[b][n][m] = sum_d Q[n][d]*K[m][d]
//   M = n, N = m, K = d.  A = Q rows (natural), B = K rows (natural).
// grid (SEQ/128 m, SEQ/128 n, BATCH), block 256
// ---------------------------------------------------------------------------
__global__ __launch_bounds__(256, 2) void scores_kernel()
{
    extern __shared__ char smem[];
    const uint32_t sb = smem_to_u32(smem);
    const int tid = threadIdx.x;
    const int b  = blockIdx.z;
    const int m0 = blockIdx.x * 128;
    const int n0 = blockIdx.y * 128;

    const __nv_bfloat16* qH = g_q_hi + ((size_t)b * SEQ + n0) * DIM;
    const __nv_bfloat16* qL = g_q_lo + ((size_t)b * SEQ + n0) * DIM;
    const __nv_bfloat16* kH = g_k_hi + ((size_t)b * SEQ + m0) * DIM;
    const __nv_bfloat16* kL = g_k_lo + ((size_t)b * SEQ + m0) * DIM;

    float acc[2][8][4] = {};

    for (int ch = 0; ch < DIM / 64; ++ch) {
        const int c0 = ch * 64;
        #pragma unroll
        for (int i = 0; i < 4; i++) {
            int idx = tid + i * 256;          // 1024 uint4s per tile
            int r   = idx >> 3;
            int c8  = (idx & 7) << 3;
            uint32_t sw = SWZ((uint32_t)(r * 128 + c8 * 2));
            size_t gofs = (size_t)r * DIM + c0 + c8;
            *(uint4*)(smem + OFF_AH + sw) = *(const uint4*)(qH + gofs);
            *(uint4*)(smem + OFF_AL + sw) = *(const uint4*)(qL + gofs);
            *(uint4*)(smem + OFF_BH + sw) = *(const uint4*)(kH + gofs);
            *(uint4*)(smem + OFF_BL + sw) = *(const uint4*)(kL + gofs);
        }
        __syncthreads();
        mma_consume(sb, acc);
        __syncthreads();
    }

    const int lane = tid & 31, wid = tid >> 5;
    const int g = lane >> 2, t = lane & 3;
    const int wm = (wid & 3) * 32, wn = (wid >> 2) * 64;
    float* S = g_scores + (size_t)b * SEQ * SEQ;
    #pragma unroll
    for (int tm = 0; tm < 2; tm++)
        #pragma unroll
        for (int h = 0; h < 2; h++) {
            int n = n0 + wm + tm * 16 + g + h * 8;
            #pragma unroll
            for (int tn = 0; tn < 8; tn++) {
                int m = m0 + wn + tn * 8 + t * 2;
                float2 v = make_float2(acc[tm][tn][2 * h], acc[tm][tn][2 * h + 1]);
                *(float2*)(S + (size_t)n * SEQ + m) = v;
            }
        }
}

// ---------------------------------------------------------------------------
// Kernel 3: row softmax; fp32 scores in, split bf16 P out.
// ---------------------------------------------------------------------------
__global__ __launch_bounds__(256) void softmax_kernel()
{
    const int row = blockIdx.x;                  // b*SEQ + n
    const float* p = g_scores + (size_t)row * SEQ;
    const int t = threadIdx.x;

    float v[8];
    float mx = -CUDART_INF_F;
    #pragma unroll
    for (int i = 0; i < 8; i++) { v[i] = p[t + i * 256]; mx = fmaxf(mx, v[i]); }

    __shared__ float red[8];
    #pragma unroll
    for (int o = 16; o > 0; o >>= 1) mx = fmaxf(mx, __shfl_xor_sync(0xffffffffu, mx, o));
    if ((t & 31) == 0) red[t >> 5] = mx;
    __syncthreads();
    mx = red[0];
    #pragma unroll
    for (int w = 1; w < 8; w++) mx = fmaxf(mx, red[w]);
    __syncthreads();

    float s = 0.f;
    #pragma unroll
    for (int i = 0; i < 8; i++) { v[i] = __expf(v[i] - mx); s += v[i]; }
    #pragma unroll
    for (int o = 16; o > 0; o >>= 1) s += __shfl_xor_sync(0xffffffffu, s, o);
    if ((t & 31) == 0) red[t >> 5] = s;
    __syncthreads();
    s = red[0];
    #pragma unroll
    for (int w = 1; w < 8; w++) s += red[w];

    const float inv = 1.0f / s;
    #pragma unroll
    for (int i = 0; i < 8; i++) {
        float pv = v[i] * inv;
        size_t off = (size_t)row * SEQ + t + i * 256;
        __nv_bfloat16 h, l; split2(pv, h, l);
        g_p_hi[off] = h;
        g_p_lo[off] = l;
    }
}

// ---------------------------------------------------------------------------
// Kernel 4: out[b][d][n] = sum_m P[n][m]*V[m][d]   (emitted transposed)
//   M = d, N = n, K = m.  A[d][m] = V[m][d] (transpose-in-load),
//   B[n][m] = P (natural).
// grid (SEQ/128 n, DIM/128 d, BATCH), block 256
// ---------------------------------------------------------------------------
__global__ __launch_bounds__(256, 2) void pv_kernel(float* __restrict__ out)
{
    extern __shared__ char smem[];
    const uint32_t sb = smem_to_u32(smem);
    const int tid = threadIdx.x;
    const int b  = blockIdx.z;
    const int n0 = blockIdx.x * 128;
    const int d0 = blockIdx.y * 128;

    const __nv_bfloat16* pH = g_p_hi + ((size_t)b * SEQ + n0) * SEQ;
    const __nv_bfloat16* pL = g_p_lo + ((size_t)b * SEQ + n0) * SEQ;
    const __nv_bfloat16* vH = g_v_hi + (size_t)b * SEQ * DIM;
    const __nv_bfloat16* vL = g_v_lo + (size_t)b * SEQ * DIM;

    float acc[2][8][4] = {};

    for (int ch = 0; ch < SEQ / 64; ++ch) {
        const int m0c = ch * 64;
        // A[d][m] = V[m][d]: coalesced read along d, scatter
        #pragma unroll
        for (int i = 0; i < 4; i++) {
            int idx = tid + i * 256;          // 1024 uint4s
            int m   = idx >> 4;               // 0..63
            int d8  = (idx & 15) << 3;        // 0..120
            size_t gofs = (size_t)(m0c + m) * DIM + d0 + d8;
            uint4 uh = *(const uint4*)(vH + gofs);
            uint4 ul = *(const uint4*)(vL + gofs);
            __nv_bfloat16 eh[8], el[8];
            *(uint4*)eh = uh; *(uint4*)el = ul;
            #pragma unroll
            for (int j = 0; j < 8; j++) {
                uint32_t sw = SWZ((uint32_t)((d8 + j) * 128 + m * 2));
                *(__nv_bfloat16*)(smem + OFF_AH + sw) = eh[j];
                *(__nv_bfloat16*)(smem + OFF_AL + sw) = el[j];
            }
        }
        // B[n][m] = P: natural copies
        #pragma unroll
        for (int i = 0; i < 4; i++) {
            int idx = tid + i * 256;
            int r   = idx >> 3;               // n row
            int c8  = (idx & 7) << 3;         // m offset
            uint32_t sw = SWZ((uint32_t)(r * 128 + c8 * 2));
            size_t gofs = (size_t)r * SEQ + m0c + c8;
            *(uint4*)(smem + OFF_BH + sw) = *(const uint4*)(pH + gofs);
            *(uint4*)(smem + OFF_BL + sw) = *(const uint4*)(pL + gofs);
        }
        __syncthreads();
        mma_consume(sb, acc);
        __syncthreads();
    }

    const int lane = tid & 31, wid = tid >> 5;
    const int g = lane >> 2, t = lane & 3;
    const int wm = (wid & 3) * 32, wn = (wid >> 2) * 64;
    float* ob = out + (size_t)b * DIM * SEQ;
    #pragma unroll
    for (int tm = 0; tm < 2; tm++)
        #pragma unroll
        for (int h = 0; h < 2; h++) {
            int d = d0 + wm + tm * 16 + g + h * 8;
            #pragma unroll
            for (int tn = 0; tn < 8; tn++) {
                int n = n0 + wn + tn * 8 + t * 2;
                float2 v = make_float2(acc[tm][tn][2 * h], acc[tm][tn][2 * h + 1]);
                *(float2*)(ob + (size_t)d * SEQ + n) = v;
            }
        }
}

// ---------------------------------------------------------------------------
extern "C" void kernel_launch(void* const* d_in, const int* in_sizes, int n_in,
                              void* d_out, int out_size)
{
    (void)in_sizes; (void)n_in; (void)out_size;
    const float* x  = (const float*)d_in[0];
    const float* Wq = (const float*)d_in[1];
    const float* bq = (const float*)d_in[2];
    const float* Wk = (const float*)d_in[3];
    const float* bk = (const float*)d_in[4];
    const float* Wv = (const float*)d_in[5];
    const float* bv = (const float*)d_in[6];
    float* out = (float*)d_out;

    cudaFuncSetAttribute(qkv_kernel,    cudaFuncAttributeMaxDynamicSharedMemorySize, SMEM_BYTES);
    cudaFuncSetAttribute(scores_kernel, cudaFuncAttributeMaxDynamicSharedMemorySize, SMEM_BYTES);
    cudaFuncSetAttribute(pv_kernel,     cudaFuncAttributeMaxDynamicSharedMemorySize, SMEM_BYTES);

    qkv_kernel<<<dim3(SEQ / 128, DIM / 128, 3 * BATCH), 256, SMEM_BYTES>>>(
        x, Wq, bq, Wk, bk, Wv, bv);
    scores_kernel<<<dim3(SEQ / 128, SEQ / 128, BATCH), 256, SMEM_BYTES>>>();
    softmax_kernel<<<BATCH * SEQ, 256>>>();
    pv_kernel<<<dim3(SEQ / 128, DIM / 128, BATCH), 256, SMEM_BYTES>>>(out);
}

// round 4
// speedup vs baseline: 3.2715x; 2.0687x over previous
#include <cuda_runtime.h>
#include <cuda_bf16.h>
#include <cstdint>
#include <math_constants.h>

constexpr int BATCH = 8;
constexpr int DIM   = 512;
constexpr int SEQ   = 2048;

// ---------------------------------------------------------------------------
// Scratch (device globals; no allocation allowed)
// ---------------------------------------------------------------------------
__device__ __align__(128) __nv_bfloat16 g_xt_hi[(size_t)BATCH * SEQ * DIM]; // [b][n][c]
__device__ __align__(128) __nv_bfloat16 g_xt_lo[(size_t)BATCH * SEQ * DIM];
__device__ __align__(128) __nv_bfloat16 g_w_hi[3][(size_t)DIM * DIM];      // [which][d][c]
__device__ __align__(128) __nv_bfloat16 g_w_lo[3][(size_t)DIM * DIM];
__device__ __align__(128) __nv_bfloat16 g_q_hi[(size_t)BATCH * SEQ * DIM]; // [b][n][d]
__device__ __align__(128) __nv_bfloat16 g_q_lo[(size_t)BATCH * SEQ * DIM];
__device__ __align__(128) __nv_bfloat16 g_k_hi[(size_t)BATCH * SEQ * DIM];
__device__ __align__(128) __nv_bfloat16 g_k_lo[(size_t)BATCH * SEQ * DIM];
__device__ __align__(128) __nv_bfloat16 g_vt_hi[(size_t)BATCH * DIM * SEQ]; // [b][d][m]
__device__ __align__(128) __nv_bfloat16 g_vt_lo[(size_t)BATCH * DIM * SEQ];
__device__ __align__(128) float         g_scores[(size_t)BATCH * SEQ * SEQ];
__device__ __align__(128) __nv_bfloat16 g_p_hi[(size_t)BATCH * SEQ * SEQ]; // [b][n][m]
__device__ __align__(128) __nv_bfloat16 g_p_lo[(size_t)BATCH * SEQ * SEQ];

// ---------------------------------------------------------------------------
// Helpers
// ---------------------------------------------------------------------------
__device__ __forceinline__ uint32_t smem_to_u32(const void* p) {
    uint32_t a;
    asm("{ .reg .u64 t; cvta.to.shared.u64 t, %1; cvt.u32.u64 %0, t; }" : "=r"(a) : "l"(p));
    return a;
}
#define SWZ(x) ((x) ^ (((x) >> 3) & 0x70))

__device__ __forceinline__ void split2(float f, __nv_bfloat16& h, __nv_bfloat16& l) {
    h = __float2bfloat16(f);
    l = __float2bfloat16(f - __bfloat162float(h));
}
__device__ __forceinline__ uint32_t pack2(__nv_bfloat16 a, __nv_bfloat16 b) {
    __nv_bfloat162 t = __halves2bfloat162(a, b);
    return *reinterpret_cast<uint32_t*>(&t);
}

__device__ __forceinline__ void ldsm_x4(uint32_t* r, uint32_t addr) {
    asm volatile("ldmatrix.sync.aligned.m8n8.x4.shared.b16 {%0,%1,%2,%3}, [%4];"
        : "=r"(r[0]), "=r"(r[1]), "=r"(r[2]), "=r"(r[3]) : "r"(addr));
}
__device__ __forceinline__ void mma16816(float* c, const uint32_t* a, const uint32_t* b) {
    asm volatile(
        "mma.sync.aligned.m16n8k16.row.col.f32.bf16.bf16.f32 "
        "{%0,%1,%2,%3}, {%4,%5,%6,%7}, {%8,%9}, {%0,%1,%2,%3};"
        : "+f"(c[0]), "+f"(c[1]), "+f"(c[2]), "+f"(c[3])
        : "r"(a[0]), "r"(a[1]), "r"(a[2]), "r"(a[3]), "r"(b[0]), "r"(b[1]));
}
__device__ __forceinline__ void cp16(uint32_t dst, const void* src) {
    asm volatile("cp.async.cg.shared.global [%0], [%1], 16;" :: "r"(dst), "l"(src));
}
#define CP_COMMIT() asm volatile("cp.async.commit_group;" ::: "memory")
#define CP_WAIT1()  asm volatile("cp.async.wait_group 1;" ::: "memory")
#define CP_WAIT0()  asm volatile("cp.async.wait_group 0;" ::: "memory")

// Per-stage smem layout: four 128x64 bf16 tiles (128B rows, SW128 swizzled)
constexpr int OFF_AH = 0;
constexpr int OFF_AL = 16384;
constexpr int OFF_BH = 32768;
constexpr int OFF_BL = 49152;
constexpr int STAGE_BYTES = 65536;
constexpr int SMEM_BYTES  = 2 * STAGE_BYTES;  // 128 KB

// Load one stage: 4 natural K-major tiles (128 rows x 64 bf16) via cp.async
__device__ __forceinline__ void load_stage(uint32_t st,
    const __nv_bfloat16* aH, const __nv_bfloat16* aL, int strideA,
    const __nv_bfloat16* bH, const __nv_bfloat16* bL, int strideB,
    int k0, int tid)
{
    #pragma unroll
    for (int i = 0; i < 4; i++) {
        int idx = tid + i * 256;
        int r   = idx >> 3;
        int c8  = (idx & 7) << 3;
        uint32_t sw = SWZ((uint32_t)(r * 128 + c8 * 2));
        size_t ga = (size_t)r * strideA + k0 + c8;
        size_t gb = (size_t)r * strideB + k0 + c8;
        cp16(st + OFF_AH + sw, aH + ga);
        cp16(st + OFF_AL + sw, aL + ga);
        cp16(st + OFF_BH + sw, bH + gb);
        cp16(st + OFF_BL + sw, bL + gb);
    }
}

// ---------------------------------------------------------------------------
// Consume one K-chunk (64): acc += AH*BH + AL*BH + AH*BL  (verified in R3).
// CTA 128x128, 8 warps as 4(M) x 2(N), warp tile 32x64.
// ---------------------------------------------------------------------------
__device__ __forceinline__ void mma_consume(uint32_t st, float acc[2][8][4]) {
    const int lane = threadIdx.x & 31;
    const int wid  = threadIdx.x >> 5;
    const int wm   = (wid & 3) * 32;
    const int wn   = (wid >> 2) * 64;

    #pragma unroll
    for (int k16 = 0; k16 < 4; k16++) {
        uint32_t aH[2][4], aL[2][4], B[4][4];
        #pragma unroll
        for (int tm = 0; tm < 2; tm++) {
            int r  = wm + tm * 16 + (lane & 15);
            int ku = k16 * 2 + (lane >> 4);
            uint32_t off = SWZ((uint32_t)(r * 128 + ku * 16));
            ldsm_x4(aH[tm], st + OFF_AH + off);
            ldsm_x4(aL[tm], st + OFF_AL + off);
        }
        #pragma unroll
        for (int tb = 0; tb < 4; tb++) {
            int g  = lane >> 3;
            int r  = wn + tb * 16 + (g >> 1) * 8 + (lane & 7);
            int ku = k16 * 2 + (g & 1);
            ldsm_x4(B[tb], st + OFF_BH + SWZ((uint32_t)(r * 128 + ku * 16)));
        }
        #pragma unroll
        for (int tm = 0; tm < 2; tm++)
            #pragma unroll
            for (int tn = 0; tn < 8; tn++) {
                uint32_t bf[2];
                bf[0] = B[tn >> 1][(tn & 1) ? 2 : 0];
                bf[1] = B[tn >> 1][(tn & 1) ? 3 : 1];
                mma16816(acc[tm][tn], aH[tm], bf);
                mma16816(acc[tm][tn], aL[tm], bf);
            }
        #pragma unroll
        for (int tb = 0; tb < 4; tb++) {
            int g  = lane >> 3;
            int r  = wn + tb * 16 + (g >> 1) * 8 + (lane & 7);
            int ku = k16 * 2 + (g & 1);
            ldsm_x4(B[tb], st + OFF_BL + SWZ((uint32_t)(r * 128 + ku * 16)));
        }
        #pragma unroll
        for (int tm = 0; tm < 2; tm++)
            #pragma unroll
            for (int tn = 0; tn < 8; tn++) {
                uint32_t bf[2];
                bf[0] = B[tn >> 1][(tn & 1) ? 2 : 0];
                bf[1] = B[tn >> 1][(tn & 1) ? 3 : 1];
                mma16816(acc[tm][tn], aH[tm], bf);
            }
    }
}

// Double-buffered GEMM driver (NC chunks of K=64)
__device__ __forceinline__ void gemm_pipeline(uint32_t sb, float acc[2][8][4],
    const __nv_bfloat16* aH, const __nv_bfloat16* aL, int strideA,
    const __nv_bfloat16* bH, const __nv_bfloat16* bL, int strideB,
    int NC, int tid)
{
    load_stage(sb, aH, aL, strideA, bH, bL, strideB, 0, tid);
    CP_COMMIT();
    for (int ch = 0; ch < NC; ++ch) {
        uint32_t cur = sb + (uint32_t)(ch & 1) * STAGE_BYTES;
        if (ch + 1 < NC) {
            uint32_t nxt = sb + (uint32_t)((ch + 1) & 1) * STAGE_BYTES;
            load_stage(nxt, aH, aL, strideA, bH, bL, strideB, (ch + 1) * 64, tid);
            CP_COMMIT();
            CP_WAIT1();
        } else {
            CP_WAIT0();
        }
        __syncthreads();
        mma_consume(cur, acc);
        __syncthreads();
    }
}

// ---------------------------------------------------------------------------
// Prep 1: split W into bf16 hi/lo.  grid (256, 3), block 256.
// ---------------------------------------------------------------------------
__global__ __launch_bounds__(256) void prep_w_kernel(
    const float* __restrict__ Wq, const float* __restrict__ Wk, const float* __restrict__ Wv)
{
    const int which = blockIdx.y;
    const float* W = (which == 0) ? Wq : (which == 1) ? Wk : Wv;
    int idx = blockIdx.x * 256 + threadIdx.x;       // float4 index, 65536 total
    float4 v = *(const float4*)(W + (size_t)idx * 4);
    __nv_bfloat16 h0,h1,h2,h3,l0,l1,l2,l3;
    split2(v.x, h0, l0); split2(v.y, h1, l1);
    split2(v.z, h2, l2); split2(v.w, h3, l3);
    *(uint2*)(&g_w_hi[which][(size_t)idx * 4]) = make_uint2(pack2(h0,h1), pack2(h2,h3));
    *(uint2*)(&g_w_lo[which][(size_t)idx * 4]) = make_uint2(pack2(l0,l1), pack2(l2,l3));
}

// ---------------------------------------------------------------------------
// Prep 2: transpose + split x[b][c][n] -> xt[b][n][c] hi/lo. 32x32 tiles.
// grid (SEQ/32, DIM/32, BATCH), block 256.
// ---------------------------------------------------------------------------
__global__ __launch_bounds__(256) void prep_x_kernel(const float* __restrict__ x)
{
    __shared__ float tile[32][33];
    const int n0 = blockIdx.x * 32;
    const int c0 = blockIdx.y * 32;
    const int b  = blockIdx.z;
    const int tid = threadIdx.x;

    {
        int c  = tid >> 3;
        int n4 = (tid & 7) << 2;
        float4 v = *(const float4*)(x + ((size_t)b * DIM + c0 + c) * SEQ + n0 + n4);
        tile[c][n4 + 0] = v.x; tile[c][n4 + 1] = v.y;
        tile[c][n4 + 2] = v.z; tile[c][n4 + 3] = v.w;
    }
    __syncthreads();
    {
        int n  = tid >> 3;
        int c4 = (tid & 7) << 2;
        float f0 = tile[c4 + 0][n], f1 = tile[c4 + 1][n];
        float f2 = tile[c4 + 2][n], f3 = tile[c4 + 3][n];
        __nv_bfloat16 h0,h1,h2,h3,l0,l1,l2,l3;
        split2(f0, h0, l0); split2(f1, h1, l1);
        split2(f2, h2, l2); split2(f3, h3, l3);
        size_t off = ((size_t)b * SEQ + n0 + n) * DIM + c0 + c4;
        *(uint2*)(g_xt_hi + off) = make_uint2(pack2(h0,h1), pack2(h2,h3));
        *(uint2*)(g_xt_lo + off) = make_uint2(pack2(l0,l1), pack2(l2,l3));
    }
}

// ---------------------------------------------------------------------------
// Kernel 1: QKV projection.  y[n][d] = sum_c xt[n][c] * W[d][c] + bias[d]
//   A = xt rows (natural), B = W rows (natural).
//   Epilogue: q,k -> [b][n][d] hi/lo;  v -> TRANSPOSED vt[b][d][n] hi/lo.
// grid (SEQ/128 n, DIM/128 d, 3*BATCH), block 256
// ---------------------------------------------------------------------------
__global__ __launch_bounds__(256, 1) void qkv_kernel(
    const float* __restrict__ bq, const float* __restrict__ bk, const float* __restrict__ bv)
{
    extern __shared__ char smem[];
    const uint32_t sb = smem_to_u32(smem);
    const int tid = threadIdx.x;
    const int z = blockIdx.z, which = z >> 3, b = z & 7;
    const float* bias = (which == 0) ? bq : (which == 1) ? bk : bv;

    const int n0 = blockIdx.x * 128;
    const int d0 = blockIdx.y * 128;

    const __nv_bfloat16* aH = g_xt_hi + ((size_t)b * SEQ + n0) * DIM;
    const __nv_bfloat16* aL = g_xt_lo + ((size_t)b * SEQ + n0) * DIM;
    const __nv_bfloat16* bH = &g_w_hi[which][(size_t)d0 * DIM];
    const __nv_bfloat16* bL = &g_w_lo[which][(size_t)d0 * DIM];

    float acc[2][8][4] = {};
    gemm_pipeline(sb, acc, aH, aL, DIM, bH, bL, DIM, DIM / 64, tid);

    const int lane = tid & 31, wid = tid >> 5;
    const int g = lane >> 2, t = lane & 3;
    const int wm = (wid & 3) * 32, wn = (wid >> 2) * 64;

    if (which < 2) {
        __nv_bfloat16* out_hi = (which == 0) ? g_q_hi : g_k_hi;
        __nv_bfloat16* out_lo = (which == 0) ? g_q_lo : g_k_lo;
        #pragma unroll
        for (int tn = 0; tn < 8; tn++) {
            const int d = d0 + wn + tn * 8 + t * 2;
            const float b0 = bias[d], b1 = bias[d + 1];
            #pragma unroll
            for (int tm = 0; tm < 2; tm++)
                #pragma unroll
                for (int h = 0; h < 2; h++) {
                    int n = n0 + wm + tm * 16 + g + h * 8;
                    float f0 = acc[tm][tn][2 * h + 0] + b0;
                    float f1 = acc[tm][tn][2 * h + 1] + b1;
                    __nv_bfloat16 h0, l0, h1, l1;
                    split2(f0, h0, l0); split2(f1, h1, l1);
                    size_t off = ((size_t)b * SEQ + n) * DIM + d;
                    *(uint32_t*)(out_hi + off) = pack2(h0, h1);
                    *(uint32_t*)(out_lo + off) = pack2(l0, l1);
                }
        }
    } else {
        // V: store transposed vt[b][d][n]
        #pragma unroll
        for (int tn = 0; tn < 8; tn++) {
            const int d = d0 + wn + tn * 8 + t * 2;
            const float b0 = bias[d], b1 = bias[d + 1];
            #pragma unroll
            for (int tm = 0; tm < 2; tm++)
                #pragma unroll
                for (int h = 0; h < 2; h++) {
                    int n = n0 + wm + tm * 16 + g + h * 8;
                    float f0 = acc[tm][tn][2 * h + 0] + b0;
                    float f1 = acc[tm][tn][2 * h + 1] + b1;
                    __nv_bfloat16 h0, l0, h1, l1;
                    split2(f0, h0, l0); split2(f1, h1, l1);
                    size_t o0 = ((size_t)b * DIM + d) * SEQ + n;
                    size_t o1 = ((size_t)b * DIM + d + 1) * SEQ + n;
                    g_vt_hi[o0] = h0; g_vt_lo[o0] = l0;
                    g_vt_hi[o1] = h1; g_vt_lo[o1] = l1;
                }
        }
    }
}

// ---------------------------------------------------------------------------
// Kernel 2: scores[b][n][m] = sum_d Q[n][d]*K[m][d].  A=Q, B=K (natural).
// grid (SEQ/128 m, SEQ/128 n, BATCH), block 256
// ---------------------------------------------------------------------------
__global__ __launch_bounds__(256, 1) void scores_kernel()
{
    extern __shared__ char smem[];
    const uint32_t sb = smem_to_u32(smem);
    const int tid = threadIdx.x;
    const int b  = blockIdx.z;
    const int m0 = blockIdx.x * 128;
    const int n0 = blockIdx.y * 128;

    const __nv_bfloat16* aH = g_q_hi + ((size_t)b * SEQ + n0) * DIM;
    const __nv_bfloat16* aL = g_q_lo + ((size_t)b * SEQ + n0) * DIM;
    const __nv_bfloat16* bH = g_k_hi + ((size_t)b * SEQ + m0) * DIM;
    const __nv_bfloat16* bL = g_k_lo + ((size_t)b * SEQ + m0) * DIM;

    float acc[2][8][4] = {};
    gemm_pipeline(sb, acc, aH, aL, DIM, bH, bL, DIM, DIM / 64, tid);

    const int lane = tid & 31, wid = tid >> 5;
    const int g = lane >> 2, t = lane & 3;
    const int wm = (wid & 3) * 32, wn = (wid >> 2) * 64;
    float* S = g_scores + (size_t)b * SEQ * SEQ;
    #pragma unroll
    for (int tm = 0; tm < 2; tm++)
        #pragma unroll
        for (int h = 0; h < 2; h++) {
            int n = n0 + wm + tm * 16 + g + h * 8;
            #pragma unroll
            for (int tn = 0; tn < 8; tn++) {
                int m = m0 + wn + tn * 8 + t * 2;
                float2 v = make_float2(acc[tm][tn][2 * h], acc[tm][tn][2 * h + 1]);
                *(float2*)(S + (size_t)n * SEQ + m) = v;
            }
        }
}

// ---------------------------------------------------------------------------
// Kernel 3: row softmax; fp32 scores in, split bf16 P out ([b][n][m]).
// ---------------------------------------------------------------------------
__global__ __launch_bounds__(256) void softmax_kernel()
{
    const int row = blockIdx.x;
    const float* p = g_scores + (size_t)row * SEQ;
    const int t = threadIdx.x;

    float v[8];
    float mx = -CUDART_INF_F;
    #pragma unroll
    for (int i = 0; i < 8; i++) { v[i] = p[t + i * 256]; mx = fmaxf(mx, v[i]); }

    __shared__ float red[8];
    #pragma unroll
    for (int o = 16; o > 0; o >>= 1) mx = fmaxf(mx, __shfl_xor_sync(0xffffffffu, mx, o));
    if ((t & 31) == 0) red[t >> 5] = mx;
    __syncthreads();
    mx = red[0];
    #pragma unroll
    for (int w = 1; w < 8; w++) mx = fmaxf(mx, red[w]);
    __syncthreads();

    float s = 0.f;
    #pragma unroll
    for (int i = 0; i < 8; i++) { v[i] = __expf(v[i] - mx); s += v[i]; }
    #pragma unroll
    for (int o = 16; o > 0; o >>= 1) s += __shfl_xor_sync(0xffffffffu, s, o);
    if ((t & 31) == 0) red[t >> 5] = s;
    __syncthreads();
    s = red[0];
    #pragma unroll
    for (int w = 1; w < 8; w++) s += red[w];

    const float inv = 1.0f / s;
    #pragma unroll
    for (int i = 0; i < 8; i++) {
        float pv = v[i] * inv;
        size_t off = (size_t)row * SEQ + t + i * 256;
        __nv_bfloat16 h, l; split2(pv, h, l);
        g_p_hi[off] = h;
        g_p_lo[off] = l;
    }
}

// ---------------------------------------------------------------------------
// Kernel 4: out[b][d][n] = sum_m vt[d][m] * P[n][m].  A=vt, B=P (natural).
// grid (SEQ/128 n, DIM/128 d, BATCH), block 256
// ---------------------------------------------------------------------------
__global__ __launch_bounds__(256, 1) void pv_kernel(float* __restrict__ out)
{
    extern __shared__ char smem[];
    const uint32_t sb = smem_to_u32(smem);
    const int tid = threadIdx.x;
    const int b  = blockIdx.z;
    const int n0 = blockIdx.x * 128;
    const int d0 = blockIdx.y * 128;

    const __nv_bfloat16* aH = g_vt_hi + ((size_t)b * DIM + d0) * SEQ;
    const __nv_bfloat16* aL = g_vt_lo + ((size_t)b * DIM + d0) * SEQ;
    const __nv_bfloat16* bH = g_p_hi + ((size_t)b * SEQ + n0) * SEQ;
    const __nv_bfloat16* bL = g_p_lo + ((size_t)b * SEQ + n0) * SEQ;

    float acc[2][8][4] = {};
    gemm_pipeline(sb, acc, aH, aL, SEQ, bH, bL, SEQ, SEQ / 64, tid);

    const int lane = tid & 31, wid = tid >> 5;
    const int g = lane >> 2, t = lane & 3;
    const int wm = (wid & 3) * 32, wn = (wid >> 2) * 64;
    float* ob = out + (size_t)b * DIM * SEQ;
    #pragma unroll
    for (int tm = 0; tm < 2; tm++)
        #pragma unroll
        for (int h = 0; h < 2; h++) {
            int d = d0 + wm + tm * 16 + g + h * 8;
            #pragma unroll
            for (int tn = 0; tn < 8; tn++) {
                int n = n0 + wn + tn * 8 + t * 2;
                float2 v = make_float2(acc[tm][tn][2 * h], acc[tm][tn][2 * h + 1]);
                *(float2*)(ob + (size_t)d * SEQ + n) = v;
            }
        }
}

// ---------------------------------------------------------------------------
extern "C" void kernel_launch(void* const* d_in, const int* in_sizes, int n_in,
                              void* d_out, int out_size)
{
    (void)in_sizes; (void)n_in; (void)out_size;
    const float* x  = (const float*)d_in[0];
    const float* Wq = (const float*)d_in[1];
    const float* bq = (const float*)d_in[2];
    const float* Wk = (const float*)d_in[3];
    const float* bk = (const float*)d_in[4];
    const float* Wv = (const float*)d_in[5];
    const float* bv = (const float*)d_in[6];
    float* out = (float*)d_out;

    cudaFuncSetAttribute(qkv_kernel,    cudaFuncAttributeMaxDynamicSharedMemorySize, SMEM_BYTES);
    cudaFuncSetAttribute(scores_kernel, cudaFuncAttributeMaxDynamicSharedMemorySize, SMEM_BYTES);
    cudaFuncSetAttribute(pv_kernel,     cudaFuncAttributeMaxDynamicSharedMemorySize, SMEM_BYTES);

    prep_w_kernel<<<dim3(256, 3), 256>>>(Wq, Wk, Wv);
    prep_x_kernel<<<dim3(SEQ / 32, DIM / 32, BATCH), 256>>>(x);
    qkv_kernel<<<dim3(SEQ / 128, DIM / 128, 3 * BATCH), 256, SMEM_BYTES>>>(bq, bk, bv);
    scores_kernel<<<dim3(SEQ / 128, SEQ / 128, BATCH), 256, SMEM_BYTES>>>();
    softmax_kernel<<<BATCH * SEQ, 256>>>();
    pv_kernel<<<dim3(SEQ / 128, DIM / 128, BATCH), 256, SMEM_BYTES>>>(out);
}